// round 14
// baseline (speedup 1.0000x reference)
#include <cuda_runtime.h>
#include <math.h>
#include <stdio.h>
#include <chrono>

// ---------------- single consolidated static scratch ----------------
// layout (float2 units):
//   A : [0        , 819200 )   8*320*320  IFFT outputs / P^T
//   B : [819200   , 1638400)   8*320*320  transpose scratch
//   C : [1638400  , 3276800)   8*320*640  640-FFT pass-1 output  [b][y][u]
//   D : [3276800  , 4915200)   8*640*320  transpose out          [b][u][y]
//   X : [4915200  , 8192000)   640*640*8  Xos BATCH-INTERLEAVED  [(u*640+v)*8+b]
#define OFF_A 0
#define OFF_B 819200
#define OFF_C 1638400
#define OFF_D 3276800
#define OFF_X 4915200
#define NBUF  8192000

__device__ float2 g_buf[NBUF];
__device__ float4 g_part[1280];   // [b][160] per-block stats partials
__device__ float4 g_norm[8];
__device__ float  g_apinv[320];
__device__ float2 g_tw[640];      // W640^m = (cos, -sin)(2pi m/640)

// ---------------- init ----------------
__global__ void k_init() {
    int t = threadIdx.x;
    if (t < 640) {
        double a = 2.0 * 3.141592653589793 * (double)t / 640.0;
        double c, s; sincos(a, &s, &c);
        g_tw[t] = make_float2((float)c, (float)(-s));
    }
    if (t < 320) {
        double beta = 3.141592653589793 * sqrt(19.45);
        double f = (t - 160.0) / 640.0;
        double w6f = 3.141592653589793 * 6.0 * f;
        double arg = beta*beta - w6f*w6f;
        double z = sqrt(arg);
        double a = sinh(z) / z;
        double a0 = sinh(beta) / beta;
        g_apinv[t] = (float)(a0 / a);
    }
}

// ---------------- complex helpers ----------------
template<bool CONJ>
__device__ __forceinline__ float2 cmulw(float2 v, float2 w) {
    float wy = CONJ ? -w.y : w.y;
    return make_float2(v.x*w.x - v.y*wy, v.x*wy + v.y*w.x);
}

template<bool CONJ>
__device__ __forceinline__ void r4(float2* s, int base, int L,
                                   float2 w1, float2 w2, float2 w3) {
    float2 t0 = s[base];
    float2 t1 = cmulw<CONJ>(s[base+L],   w1);
    float2 t2 = cmulw<CONJ>(s[base+2*L], w2);
    float2 t3 = cmulw<CONJ>(s[base+3*L], w3);
    float e0r=t0.x+t2.x, e0i=t0.y+t2.y;
    float e1r=t0.x-t2.x, e1i=t0.y-t2.y;
    float o0r=t1.x+t3.x, o0i=t1.y+t3.y;
    float o1r=t1.x-t3.x, o1i=t1.y-t3.y;
    s[base]     = make_float2(e0r+o0r, e0i+o0i);
    s[base+2*L] = make_float2(e0r-o0r, e0i-o0i);
    if (!CONJ) {
        s[base+L]   = make_float2(e1r+o1i, e1i-o1r);
        s[base+3*L] = make_float2(e1r-o1i, e1i+o1r);
    } else {
        s[base+L]   = make_float2(e1r-o1i, e1i+o1r);
        s[base+3*L] = make_float2(e1r+o1i, e1i-o1r);
    }
}

__device__ __forceinline__ int drev4(int j) {
    return ((j & 3) << 4) | (j & 12) | (j >> 4);
}

// ---------------- 320-pt FFT radix-4 stages ----------------
template<bool CONJ>
__device__ __forceinline__ void fft320_stages(float2* srow, int rt, int obase) {
    int g = rt >> 4, bf = rt & 15;
    float2* s = srow + g*64;
    __syncthreads();
    r4<CONJ>(s, bf*4, 1, g_tw[0], g_tw[0], g_tw[0]);
    __syncthreads();
    {
        int j = bf & 3, base = (bf >> 2)*16 + j;
        r4<CONJ>(s, base, 4, g_tw[j*40], g_tw[j*80], g_tw[j*120]);
    }
    __syncthreads();
    r4<CONJ>(s, bf, 16, g_tw[bf*10], g_tw[bf*20], g_tw[bf*30]);
    __syncthreads();
    if (rt < 64) {
        float2 z[5];
        z[0] = srow[rt];
        #pragma unroll
        for (int n1 = 1; n1 < 5; n1++)
            z[n1] = cmulw<CONJ>(srow[n1*64 + rt], g_tw[2*n1*rt]);
        const float W5R[5] = {1.f, 0.309016994374947f, -0.809016994374947f, -0.809016994374947f, 0.309016994374947f};
        const float W5I[5] = {0.f, 0.951056516295154f, 0.587785252292473f, -0.587785252292473f, -0.951056516295154f};
        const float s5 = CONJ ? 1.f : -1.f;
        #pragma unroll
        for (int k1 = 0; k1 < 5; k1++) {
            float ar = z[0].x, ai = z[0].y;
            #pragma unroll
            for (int n1 = 1; n1 < 5; n1++) {
                int q = (n1 * k1) % 5;
                float wr = W5R[q], wi = s5 * W5I[q];
                ar += wr*z[n1].x - wi*z[n1].y;
                ai += wr*z[n1].y + wi*z[n1].x;
            }
            g_buf[obase + rt + 64*k1] = make_float2(ar, ai);
        }
    }
}

// 640-pt forward FFT stages; INTERLEAVE store X[(u*640+v)*8+b] via obase stepping.
template<bool INTERLEAVE>
__device__ __forceinline__ void fft640_stages(float2* srow, int rt, int obase) {
    int g = rt >> 5, bf = rt & 31;
    float2* s = srow + g*128;
    __syncthreads();
    {
        int j = bf & 1, base = (bf >> 1)*8 + j;
        r4<false>(s, base, 2, g_tw[j*80], g_tw[j*160], g_tw[j*240]);
    }
    __syncthreads();
    {
        int j = bf & 7, base = (bf >> 3)*32 + j;
        r4<false>(s, base, 8, g_tw[j*20], g_tw[j*40], g_tw[j*60]);
    }
    __syncthreads();
    r4<false>(s, bf, 32, g_tw[bf*5], g_tw[bf*10], g_tw[bf*15]);
    __syncthreads();
    if (rt < 128) {
        float2 z[5];
        z[0] = srow[rt];
        #pragma unroll
        for (int n1 = 1; n1 < 5; n1++)
            z[n1] = cmulw<false>(srow[n1*128 + rt], g_tw[n1*rt]);
        const float W5R[5] = {1.f, 0.309016994374947f, -0.809016994374947f, -0.809016994374947f, 0.309016994374947f};
        const float W5I[5] = {0.f, 0.951056516295154f, 0.587785252292473f, -0.587785252292473f, -0.951056516295154f};
        #pragma unroll
        for (int k1 = 0; k1 < 5; k1++) {
            float ar = z[0].x, ai = z[0].y;
            #pragma unroll
            for (int n1 = 1; n1 < 5; n1++) {
                int q = (n1 * k1) % 5;
                float wr = W5R[q], wi = -W5I[q];
                ar += wr*z[n1].x - wi*z[n1].y;
                ai += wr*z[n1].y + wi*z[n1].x;
            }
            g_buf[obase + (INTERLEAVE ? (rt*8 + k1*1024) : (rt + 128*k1))] = make_float2(ar, ai);
        }
    }
}

// ---------------- phase 1a ----------------
__global__ __launch_bounds__(160) void k_ifft320_a(const float* __restrict__ kr,
                                                   const float* __restrict__ ki) {
    __shared__ float2 sh[2][320];
    int r = threadIdx.x / 80, rt = threadIdx.x % 80;
    int b = blockIdx.y, u = blockIdx.x*2 + r;
    int rowbase = (b*320 + u)*320;
    #pragma unroll
    for (int i = 0; i < 4; i++) {
        int e = rt + 80*i;
        int g = e >> 6, j = e & 63;
        int src = rowbase + g + 5*drev4(j);
        sh[r][e] = make_float2(__ldg(&kr[src]), __ldg(&ki[src]));
    }
    fft320_stages<true>(sh[r], rt, OFF_A + rowbase);
}

// ---------------- phase 1b: IFFT cols + fused stats ----------------
__global__ __launch_bounds__(160) void k_ifft320_b() {
    __shared__ float2 sh[2][320];
    __shared__ float4 warpsum[5];
    int r = threadIdx.x / 80, rt = threadIdx.x % 80;
    int b = blockIdx.y, y = blockIdx.x*2 + r;
    int rowbase = (b*320 + y)*320;
    #pragma unroll
    for (int i = 0; i < 4; i++) {
        int e = rt + 80*i;
        int g = e >> 6, j = e & 63;
        sh[r][e] = g_buf[OFF_B + rowbase + g + 5*drev4(j)];
    }
    float2* srow = sh[r];
    {
        int g = rt >> 4, bf = rt & 15;
        float2* s = srow + g*64;
        __syncthreads();
        r4<true>(s, bf*4, 1, g_tw[0], g_tw[0], g_tw[0]);
        __syncthreads();
        {
            int j = bf & 3, base = (bf >> 2)*16 + j;
            r4<true>(s, base, 4, g_tw[j*40], g_tw[j*80], g_tw[j*120]);
        }
        __syncthreads();
        r4<true>(s, bf, 16, g_tw[bf*10], g_tw[bf*20], g_tw[bf*30]);
        __syncthreads();
    }
    float sR = 0.f, sR2 = 0.f, sI = 0.f, sI2 = 0.f;
    if (rt < 64) {
        float2 z[5];
        z[0] = srow[rt];
        #pragma unroll
        for (int n1 = 1; n1 < 5; n1++)
            z[n1] = cmulw<true>(srow[n1*64 + rt], g_tw[2*n1*rt]);
        const float W5R[5] = {1.f, 0.309016994374947f, -0.809016994374947f, -0.809016994374947f, 0.309016994374947f};
        const float W5I[5] = {0.f, 0.951056516295154f, 0.587785252292473f, -0.587785252292473f, -0.951056516295154f};
        #pragma unroll
        for (int k1 = 0; k1 < 5; k1++) {
            float ar = z[0].x, ai = z[0].y;
            #pragma unroll
            for (int n1 = 1; n1 < 5; n1++) {
                int q = (n1 * k1) % 5;
                float wr = W5R[q], wi = W5I[q];
                ar += wr*z[n1].x - wi*z[n1].y;
                ai += wr*z[n1].y + wi*z[n1].x;
            }
            int x = rt + 64*k1;
            g_buf[OFF_A + rowbase + x] = make_float2(ar, ai);
            float sg = ((x + y) & 1) ? -1.f : 1.f;
            sR  += sg * ar;
            sR2 += ar * ar;
            sI  += sg * ai;
            sI2 += ai * ai;
        }
    }
    #pragma unroll
    for (int o = 16; o > 0; o >>= 1) {
        sR  += __shfl_down_sync(0xffffffff, sR,  o);
        sR2 += __shfl_down_sync(0xffffffff, sR2, o);
        sI  += __shfl_down_sync(0xffffffff, sI,  o);
        sI2 += __shfl_down_sync(0xffffffff, sI2, o);
    }
    int lane = threadIdx.x & 31, wid = threadIdx.x >> 5;
    if (lane == 0) warpsum[wid] = make_float4(sR, sR2, sI, sI2);
    __syncthreads();
    if (threadIdx.x == 0) {
        float4 t = warpsum[0];
        #pragma unroll
        for (int w = 1; w < 5; w++) {
            float4 u2 = warpsum[w];
            t.x += u2.x; t.y += u2.y; t.z += u2.z; t.w += u2.w;
        }
        g_part[b*160 + blockIdx.x] = t;
    }
}

__global__ void k_fin() {
    int b = threadIdx.x;
    if (b >= 8) return;
    double sR = 0, sR2 = 0, sI = 0, sI2 = 0;
    for (int j = 0; j < 160; j++) {
        float4 t = g_part[b*160 + j];
        sR += t.x; sR2 += t.y; sI += t.z; sI2 += t.w;
    }
    const double N = 102400.0;
    double sv_r = sR / 320.0;
    double sq_r = sR2 / 102400.0;
    double sv_i = sI / 320.0;
    double sq_i = sI2 / 102400.0;
    double mR = sv_r / N;
    double vR = (sq_r - sv_r*sv_r/N) / (N - 1.0);
    double mI = sv_i / N;
    double vI = (sq_i - sv_i*sv_i/N) / (N - 1.0);
    g_norm[b] = make_float4((float)mR, (float)(1.0/sqrt(vR)),
                            (float)mI, (float)(1.0/sqrt(vI)));
}

// ---------------- transposes ----------------
__global__ void k_trans320() {
    __shared__ float2 tile[32][33];
    int b = blockIdx.z;
    int base = b*320*320;
    int c = blockIdx.x*32 + threadIdx.x;
    int r0 = blockIdx.y*32;
    #pragma unroll
    for (int i = threadIdx.y; i < 32; i += 8)
        tile[i][threadIdx.x] = g_buf[OFF_A + base + (r0 + i)*320 + c];
    __syncthreads();
    int oc = r0 + threadIdx.x;
    int or0 = blockIdx.x*32;
    #pragma unroll
    for (int i = threadIdx.y; i < 32; i += 8)
        g_buf[OFF_B + base + (or0 + i)*320 + oc] = tile[threadIdx.x][i];
}

// C [b][y][u] -> D [b][u][y]
__global__ void k_trans640() {
    __shared__ float2 tile[32][33];
    int b = blockIdx.z;
    int c = blockIdx.x*32 + threadIdx.x;
    int r0 = blockIdx.y*32;
    #pragma unroll
    for (int i = threadIdx.y; i < 32; i += 8)
        tile[i][threadIdx.x] = g_buf[OFF_C + b*320*640 + (r0 + i)*640 + c];
    __syncthreads();
    int oc = r0 + threadIdx.x;
    int or0 = blockIdx.x*32;
    #pragma unroll
    for (int i = threadIdx.y; i < 32; i += 8)
        g_buf[OFF_D + b*640*320 + (or0 + i)*320 + oc] = tile[threadIdx.x][i];
}

// ---------------- phase 2a: FFT along x ----------------
__global__ __launch_bounds__(320) void k_fft640_a() {
    __shared__ float2 sh[2][640];
    int r = threadIdx.x / 160, rt = threadIdx.x % 160;
    int b = blockIdx.y, y = blockIdx.x*2 + r;
    float4 nm = g_norm[b];
    int yy = (y < 160) ? y + 160 : y - 160;
    float apy = g_apinv[y];
    #pragma unroll
    for (int i = 0; i < 2; i++) {
        int pk = rt + 160*i;
        int g = pk >> 6, k = pk & 63;
        int x = g + 5*drev4(k);
        int xx = (x < 160) ? x + 160 : x - 160;
        float2 p = g_buf[OFF_A + (b*320 + yy)*320 + xx];
        float c = ((x + y) & 1) ? -0.003125f : 0.003125f;
        float re = (c*p.x - nm.x) * nm.y;
        float im = (c*p.y - nm.z) * nm.w;
        float sc = apy * g_apinv[x];
        float2 v = make_float2(re*sc, im*sc);
        sh[r][g*128 + 2*k]     = v;
        sh[r][g*128 + 2*k + 1] = v;
    }
    fft640_stages<false>(sh[r], rt, OFF_C + (b*320 + y)*640);
}

// ---------------- phase 2b: FFT along y, interleaved X store ----------------
__global__ __launch_bounds__(320) void k_fft640_b() {
    __shared__ float2 sh[2][640];
    int r = threadIdx.x / 160, rt = threadIdx.x % 160;
    int b = blockIdx.y, u = blockIdx.x*2 + r;
    #pragma unroll
    for (int i = 0; i < 2; i++) {
        int pk = rt + 160*i;
        int g = pk >> 6, k = pk & 63;
        int src = g + 5*drev4(k);
        float2 v = g_buf[OFF_D + b*640*320 + u*320 + src];
        sh[r][g*128 + 2*k]     = v;
        sh[r][g*128 + 2*k + 1] = v;
    }
    fft640_stages<true>(sh[r], rt, OFF_X + u*640*8 + b);
}

// ---------------- KB i0 and gather ----------------
__device__ __forceinline__ float i0f(float x) {
    if (x < 3.75f) {
        float t = x * (1.0f/3.75f); float t2 = t*t;
        return 1.0f + t2*(3.5156229f + t2*(3.0899424f + t2*(1.2067492f +
               t2*(0.2659732f + t2*(0.0360768f + t2*0.0045813f)))));
    } else {
        float t = 3.75f / x;
        float p = 0.39894228f + t*(0.01328592f + t*(0.00225319f + t*(-0.00157565f +
                  t*(0.00916281f + t*(-0.02057706f + t*(0.02635537f +
                  t*(-0.01647633f + t*0.00392377f)))))));
        return __expf(x) * rsqrtf(x) * p;
    }
}

__global__ __launch_bounds__(256) void k_gather(const float* __restrict__ tkx,
                                                const float* __restrict__ tky,
                                                float* __restrict__ out) {
    int p = blockIdx.x*256 + threadIdx.x;
    if (p >= 512000) return;
    const float beta = (float)(3.141592653589793 * sqrt(19.45));
    const float inv_i0b = 1.0f / i0f(beta);
    float gx = __ldg(&tkx[p]) * 2.0f;
    float gy = __ldg(&tky[p]) * 2.0f;
    if (!(gx > -321.f && gx < 321.f)) gx = 0.f;
    if (!(gy > -321.f && gy < 321.f)) gy = 0.f;
    int ix0 = (int)floorf(gx) - 2;
    int iy0 = (int)floorf(gy) - 2;
    float axr[6], axi[6], ayr[6], ayi[6];
    int ixm[6], iym[6];
    #pragma unroll
    for (int j = 0; j < 6; j++) {
        {
            float d = gx - (float)(ix0 + j);
            float arg = fmaxf(1.0f - d*d*(1.0f/9.0f), 0.0f);
            float w = i0f(beta * sqrtf(arg)) * inv_i0b;
            int q = (ix0 + j + 1024) & 3;
            axr[j] = (q == 0) ? w : ((q == 2) ? -w : 0.f);
            axi[j] = (q == 1) ? w : ((q == 3) ? -w : 0.f);
            int v = ix0 + j; if (v < 0) v += 640;
            ixm[j] = v;
        }
        {
            float d = gy - (float)(iy0 + j);
            float arg = fmaxf(1.0f - d*d*(1.0f/9.0f), 0.0f);
            float w = i0f(beta * sqrtf(arg)) * inv_i0b;
            int q = (iy0 + j + 1024) & 3;
            ayr[j] = (q == 0) ? w : ((q == 2) ? -w : 0.f);
            ayi[j] = (q == 1) ? w : ((q == 3) ? -w : 0.f);
            int v = iy0 + j; if (v < 0) v += 640;
            iym[j] = v;
        }
    }
    float acc0=0.f, acc1=0.f, acc2=0.f, acc3=0.f;
    float acc4=0.f, acc5=0.f, acc6=0.f, acc7=0.f;
    #pragma unroll
    for (int jx = 0; jx < 6; jx++) {
        const float2* rowb = g_buf + OFF_X + ixm[jx]*(640*8);
        float wxr = axr[jx], wxi = axi[jx];
        #pragma unroll
        for (int jy = 0; jy < 6; jy++) {
            float wr = wxr*ayr[jy] - wxi*ayi[jy];
            float wi = wxr*ayi[jy] + wxi*ayr[jy];
            const float4* cell = (const float4*)(rowb + iym[jy]*8);
            float4 v0 = __ldg(&cell[0]);
            float4 v1 = __ldg(&cell[1]);
            float4 v2 = __ldg(&cell[2]);
            float4 v3 = __ldg(&cell[3]);
            acc0 += wr*v0.x - wi*v0.y;
            acc1 += wr*v0.z - wi*v0.w;
            acc2 += wr*v1.x - wi*v1.y;
            acc3 += wr*v1.z - wi*v1.w;
            acc4 += wr*v2.x - wi*v2.y;
            acc5 += wr*v2.z - wi*v2.w;
            acc6 += wr*v3.x - wi*v3.y;
            acc7 += wr*v3.z - wi*v3.w;
        }
    }
    out[            p] = acc0;
    out[ 512000 + p] = acc1;
    out[1024000 + p] = acc2;
    out[1536000 + p] = acc3;
    out[2048000 + p] = acc4;
    out[2560000 + p] = acc5;
    out[3072000 + p] = acc6;
    out[3584000 + p] = acc7;
}

// ---------------- host launcher with diag-only per-kernel timing ----------------
static int is_capturing_now() {
    cudaStreamCaptureStatus st = cudaStreamCaptureStatusNone;
    cudaError_t e = cudaStreamIsCapturing(0, &st);
    if (e != cudaSuccess) { cudaGetLastError(); return 1; }
    return st != cudaStreamCaptureStatusNone;
}

extern "C" void kernel_launch(void* const* d_in, const int* in_sizes, int n_in,
                              void* d_out, int out_size) {
    const float *kr = 0, *ki = 0, *tkx = 0, *tky = 0;
    for (int i = 0; i < n_in; i++) {
        int s = in_sizes[i];
        if (s == 819200) {
            if (!kr) kr = (const float*)d_in[i];
            else if (!ki) ki = (const float*)d_in[i];
        } else if (s == 512000) {
            if (!tkx) tkx = (const float*)d_in[i];
            else if (!tky) tky = (const float*)d_in[i];
        }
    }
    if ((!kr || !ki || !tkx || !tky) && n_in >= 4) {
        kr  = (const float*)d_in[0];
        ki  = (const float*)d_in[1];
        tkx = (const float*)d_in[2];
        tky = (const float*)d_in[3];
    }
    if (!kr || !ki || !tkx || !tky || !d_out) return;
    float* out = (float*)d_out;

    const int diag = !is_capturing_now();

#define TIMED(tag, stmt) do { \
    if (diag) { \
        cudaDeviceSynchronize(); \
        auto _t0 = std::chrono::steady_clock::now(); \
        stmt; \
        cudaDeviceSynchronize(); \
        auto _t1 = std::chrono::steady_clock::now(); \
        fprintf(stderr, "[t] %-12s %8.1f us\n", tag, \
                std::chrono::duration<double, std::micro>(_t1 - _t0).count()); \
        fflush(stderr); \
    } else { stmt; } \
} while (0)

    TIMED("init",      (k_init<<<1, 640>>>()));
    TIMED("ifft320_a", (k_ifft320_a<<<dim3(160, 8), 160>>>(kr, ki)));
    TIMED("trans320",  (k_trans320<<<dim3(10, 10, 8), dim3(32, 8)>>>()));
    TIMED("ifft320_b", (k_ifft320_b<<<dim3(160, 8), 160>>>()));
    TIMED("fin",       (k_fin<<<1, 32>>>()));
    TIMED("fft640_a",  (k_fft640_a<<<dim3(160, 8), 320>>>()));
    TIMED("trans640",  (k_trans640<<<dim3(20, 10, 8), dim3(32, 8)>>>()));
    TIMED("fft640_b",  (k_fft640_b<<<dim3(320, 8), 320>>>()));
    TIMED("gather",    (k_gather<<<2000, 256>>>(tkx, tky, out)));
#undef TIMED
}

// round 15
// speedup vs baseline: 1.6000x; 1.6000x over previous
#include <cuda_runtime.h>
#include <math.h>

// ---------------- single consolidated static scratch ----------------
// float2 units: A[0,819200) B[819200,1638400) C[1638400,3276800) D[3276800,4915200)
// float units (overlaying tail of g_buf):
//   XR : floats [9830400 , 13107200)  real plane,  Xr[(u*640+v)*8 + b]
//   XI : floats [13107200, 16384000)  imag plane
#define OFF_A 0
#define OFF_B 819200
#define OFF_C 1638400
#define OFF_D 3276800
#define XR0F  9830400
#define XI0F  13107200
#define NBUF  8192000

__device__ float2 g_buf[NBUF];
__device__ float4 g_part[200];    // [b][25] stats partials
__device__ float4 g_norm[8];
__device__ float  g_apinv[320];
__device__ float2 g_tw[640];      // W640^m = (cos, -sin)(2pi m/640)

// ---------------- init ----------------
__global__ void k_init() {
    int t = threadIdx.x;
    if (t < 640) {
        double a = 2.0 * 3.141592653589793 * (double)t / 640.0;
        double c, s; sincos(a, &s, &c);
        g_tw[t] = make_float2((float)c, (float)(-s));
    }
    if (t < 320) {
        double beta = 3.141592653589793 * sqrt(19.45);
        double f = (t - 160.0) / 640.0;
        double w6f = 3.141592653589793 * 6.0 * f;
        double arg = beta*beta - w6f*w6f;
        double z = sqrt(arg);
        double a = sinh(z) / z;
        double a0 = sinh(beta) / beta;
        g_apinv[t] = (float)(a0 / a);
    }
}

// ---------------- complex helpers ----------------
template<bool CONJ>
__device__ __forceinline__ float2 cmulw(float2 v, float2 w) {
    float wy = CONJ ? -w.y : w.y;
    return make_float2(v.x*w.x - v.y*wy, v.x*wy + v.y*w.x);
}

template<bool CONJ>
__device__ __forceinline__ void r4(float2* s, int base, int L,
                                   float2 w1, float2 w2, float2 w3) {
    float2 t0 = s[base];
    float2 t1 = cmulw<CONJ>(s[base+L],   w1);
    float2 t2 = cmulw<CONJ>(s[base+2*L], w2);
    float2 t3 = cmulw<CONJ>(s[base+3*L], w3);
    float e0r=t0.x+t2.x, e0i=t0.y+t2.y;
    float e1r=t0.x-t2.x, e1i=t0.y-t2.y;
    float o0r=t1.x+t3.x, o0i=t1.y+t3.y;
    float o1r=t1.x-t3.x, o1i=t1.y-t3.y;
    s[base]     = make_float2(e0r+o0r, e0i+o0i);
    s[base+2*L] = make_float2(e0r-o0r, e0i-o0i);
    if (!CONJ) {
        s[base+L]   = make_float2(e1r+o1i, e1i-o1r);
        s[base+3*L] = make_float2(e1r-o1i, e1i+o1r);
    } else {
        s[base+L]   = make_float2(e1r-o1i, e1i+o1r);
        s[base+3*L] = make_float2(e1r+o1i, e1i-o1r);
    }
}

__device__ __forceinline__ int drev4(int j) {
    return ((j & 3) << 4) | (j & 12) | (j >> 4);
}

// ---------------- 320-pt FFT stages ----------------
template<bool CONJ>
__device__ __forceinline__ void fft320_stages(float2* srow, int rt, int obase) {
    int g = rt >> 4, bf = rt & 15;
    float2* s = srow + g*64;
    __syncthreads();
    r4<CONJ>(s, bf*4, 1, g_tw[0], g_tw[0], g_tw[0]);
    __syncthreads();
    {
        int j = bf & 3, base = (bf >> 2)*16 + j;
        r4<CONJ>(s, base, 4, g_tw[j*40], g_tw[j*80], g_tw[j*120]);
    }
    __syncthreads();
    r4<CONJ>(s, bf, 16, g_tw[bf*10], g_tw[bf*20], g_tw[bf*30]);
    __syncthreads();
    if (rt < 64) {
        float2 z[5];
        z[0] = srow[rt];
        #pragma unroll
        for (int n1 = 1; n1 < 5; n1++)
            z[n1] = cmulw<CONJ>(srow[n1*64 + rt], g_tw[2*n1*rt]);
        const float W5R[5] = {1.f, 0.309016994374947f, -0.809016994374947f, -0.809016994374947f, 0.309016994374947f};
        const float W5I[5] = {0.f, 0.951056516295154f, 0.587785252292473f, -0.587785252292473f, -0.951056516295154f};
        const float s5 = CONJ ? 1.f : -1.f;
        #pragma unroll
        for (int k1 = 0; k1 < 5; k1++) {
            float ar = z[0].x, ai = z[0].y;
            #pragma unroll
            for (int n1 = 1; n1 < 5; n1++) {
                int q = (n1 * k1) % 5;
                float wr = W5R[q], wi = s5 * W5I[q];
                ar += wr*z[n1].x - wi*z[n1].y;
                ai += wr*z[n1].y + wi*z[n1].x;
            }
            g_buf[obase + rt + 64*k1] = make_float2(ar, ai);
        }
    }
}

// ---------------- phase 1 ----------------
__global__ __launch_bounds__(160) void k_ifft320_a(const float* __restrict__ kr,
                                                   const float* __restrict__ ki) {
    __shared__ float2 sh[2][320];
    int r = threadIdx.x / 80, rt = threadIdx.x % 80;
    int b = blockIdx.y, u = blockIdx.x*2 + r;
    int rowbase = (b*320 + u)*320;
    #pragma unroll
    for (int i = 0; i < 4; i++) {
        int e = rt + 80*i;
        int g = e >> 6, j = e & 63;
        int src = rowbase + g + 5*drev4(j);
        sh[r][e] = make_float2(__ldg(&kr[src]), __ldg(&ki[src]));
    }
    fft320_stages<true>(sh[r], rt, OFF_A + rowbase);
}

__global__ __launch_bounds__(160) void k_ifft320_b() {
    __shared__ float2 sh[2][320];
    int r = threadIdx.x / 80, rt = threadIdx.x % 80;
    int b = blockIdx.y, y = blockIdx.x*2 + r;
    int rowbase = (b*320 + y)*320;
    #pragma unroll
    for (int i = 0; i < 4; i++) {
        int e = rt + 80*i;
        int g = e >> 6, j = e & 63;
        sh[r][e] = g_buf[OFF_B + rowbase + g + 5*drev4(j)];
    }
    fft320_stages<true>(sh[r], rt, OFF_A + rowbase);
}

// ---------------- transposes ----------------
__global__ void k_trans320() {
    __shared__ float2 tile[32][33];
    int b = blockIdx.z;
    int base = b*320*320;
    int c = blockIdx.x*32 + threadIdx.x;
    int r0 = blockIdx.y*32;
    #pragma unroll
    for (int i = threadIdx.y; i < 32; i += 8)
        tile[i][threadIdx.x] = g_buf[OFF_A + base + (r0 + i)*320 + c];
    __syncthreads();
    int oc = r0 + threadIdx.x;
    int or0 = blockIdx.x*32;
    #pragma unroll
    for (int i = threadIdx.y; i < 32; i += 8)
        g_buf[OFF_B + base + (or0 + i)*320 + oc] = tile[threadIdx.x][i];
}

// C [b][y][u] -> D [b][u][y]
__global__ void k_trans640() {
    __shared__ float2 tile[32][33];
    int b = blockIdx.z;
    int c = blockIdx.x*32 + threadIdx.x;
    int r0 = blockIdx.y*32;
    #pragma unroll
    for (int i = threadIdx.y; i < 32; i += 8)
        tile[i][threadIdx.x] = g_buf[OFF_C + b*320*640 + (r0 + i)*640 + c];
    __syncthreads();
    int oc = r0 + threadIdx.x;
    int or0 = blockIdx.x*32;
    #pragma unroll
    for (int i = threadIdx.y; i < 32; i += 8)
        g_buf[OFF_D + b*640*320 + (or0 + i)*320 + oc] = tile[threadIdx.x][i];
}

// ---------------- reduction (separate, as in best-measured R12) ----------------
__global__ __launch_bounds__(256) void k_reduce() {
    __shared__ float4 warpsum[8];
    int b = blockIdx.y;
    float sR = 0.f, sR2 = 0.f, sI = 0.f, sI2 = 0.f;
    int base = blockIdx.x*4096;
    #pragma unroll
    for (int i = 0; i < 16; i++) {
        int idx = base + threadIdx.x + i*256;
        float2 v = g_buf[OFF_A + b*102400 + idx];
        int y = idx / 320;
        int x = idx - y*320;
        float sg = ((x + y) & 1) ? -1.f : 1.f;
        sR  += sg * v.x;
        sR2 += v.x * v.x;
        sI  += sg * v.y;
        sI2 += v.y * v.y;
    }
    #pragma unroll
    for (int o = 16; o > 0; o >>= 1) {
        sR  += __shfl_down_sync(0xffffffff, sR,  o);
        sR2 += __shfl_down_sync(0xffffffff, sR2, o);
        sI  += __shfl_down_sync(0xffffffff, sI,  o);
        sI2 += __shfl_down_sync(0xffffffff, sI2, o);
    }
    int lane = threadIdx.x & 31, wid = threadIdx.x >> 5;
    if (lane == 0) warpsum[wid] = make_float4(sR, sR2, sI, sI2);
    __syncthreads();
    if (threadIdx.x == 0) {
        float4 t = warpsum[0];
        #pragma unroll
        for (int w = 1; w < 8; w++) {
            float4 u = warpsum[w];
            t.x += u.x; t.y += u.y; t.z += u.z; t.w += u.w;
        }
        g_part[b*25 + blockIdx.x] = t;
    }
}

__global__ void k_fin() {
    int b = threadIdx.x;
    if (b >= 8) return;
    double sR = 0, sR2 = 0, sI = 0, sI2 = 0;
    for (int j = 0; j < 25; j++) {
        float4 t = g_part[b*25 + j];
        sR += t.x; sR2 += t.y; sI += t.z; sI2 += t.w;
    }
    const double N = 102400.0;
    double sv_r = sR / 320.0;
    double sq_r = sR2 / 102400.0;
    double sv_i = sI / 320.0;
    double sq_i = sI2 / 102400.0;
    double mR = sv_r / N;
    double vR = (sq_r - sv_r*sv_r/N) / (N - 1.0);
    double mI = sv_i / N;
    double vI = (sq_i - sv_i*sv_i/N) / (N - 1.0);
    g_norm[b] = make_float4((float)mR, (float)(1.0/sqrt(vR)),
                            (float)mI, (float)(1.0/sqrt(vI)));
}

// ---------------- phase 2a: FFT along x ----------------
__global__ __launch_bounds__(320) void k_fft640_a() {
    __shared__ float2 sh[2][640];
    int r = threadIdx.x / 160, rt = threadIdx.x % 160;
    int b = blockIdx.y, y = blockIdx.x*2 + r;
    float4 nm = g_norm[b];
    int yy = (y < 160) ? y + 160 : y - 160;
    float apy = g_apinv[y];
    #pragma unroll
    for (int i = 0; i < 2; i++) {
        int pk = rt + 160*i;
        int g = pk >> 6, k = pk & 63;
        int x = g + 5*drev4(k);
        int xx = (x < 160) ? x + 160 : x - 160;
        float2 p = g_buf[OFF_A + (b*320 + yy)*320 + xx];
        float c = ((x + y) & 1) ? -0.003125f : 0.003125f;
        float re = (c*p.x - nm.x) * nm.y;
        float im = (c*p.y - nm.z) * nm.w;
        float sc = apy * g_apinv[x];
        float2 v = make_float2(re*sc, im*sc);
        sh[r][g*128 + 2*k]     = v;
        sh[r][g*128 + 2*k + 1] = v;
    }
    // stages + contiguous row store to C
    float2* srow = sh[r];
    {
        int g = rt >> 5, bf = rt & 31;
        float2* s = srow + g*128;
        __syncthreads();
        { int j = bf & 1, base = (bf >> 1)*8 + j;
          r4<false>(s, base, 2, g_tw[j*80], g_tw[j*160], g_tw[j*240]); }
        __syncthreads();
        { int j = bf & 7, base = (bf >> 3)*32 + j;
          r4<false>(s, base, 8, g_tw[j*20], g_tw[j*40], g_tw[j*60]); }
        __syncthreads();
        r4<false>(s, bf, 32, g_tw[bf*5], g_tw[bf*10], g_tw[bf*15]);
        __syncthreads();
        if (rt < 128) {
            float2 z[5];
            z[0] = srow[rt];
            #pragma unroll
            for (int n1 = 1; n1 < 5; n1++)
                z[n1] = cmulw<false>(srow[n1*128 + rt], g_tw[n1*rt]);
            const float W5R[5] = {1.f, 0.309016994374947f, -0.809016994374947f, -0.809016994374947f, 0.309016994374947f};
            const float W5I[5] = {0.f, 0.951056516295154f, 0.587785252292473f, -0.587785252292473f, -0.951056516295154f};
            int obase = OFF_C + (b*320 + y)*640;
            #pragma unroll
            for (int k1 = 0; k1 < 5; k1++) {
                float ar = z[0].x, ai = z[0].y;
                #pragma unroll
                for (int n1 = 1; n1 < 5; n1++) {
                    int q = (n1 * k1) % 5;
                    float wr = W5R[q], wi = -W5I[q];
                    ar += wr*z[n1].x - wi*z[n1].y;
                    ai += wr*z[n1].y + wi*z[n1].x;
                }
                g_buf[obase + rt + 128*k1] = make_float2(ar, ai);
            }
        }
    }
}

// ---------------- phase 2b: FFT along y -> split Xr/Xi planes ----------------
__global__ __launch_bounds__(320) void k_fft640_b() {
    __shared__ float2 sh[2][640];
    int r = threadIdx.x / 160, rt = threadIdx.x % 160;
    int b = blockIdx.y, u = blockIdx.x*2 + r;
    #pragma unroll
    for (int i = 0; i < 2; i++) {
        int pk = rt + 160*i;
        int g = pk >> 6, k = pk & 63;
        int src = g + 5*drev4(k);
        float2 v = g_buf[OFF_D + b*640*320 + u*320 + src];
        sh[r][g*128 + 2*k]     = v;
        sh[r][g*128 + 2*k + 1] = v;
    }
    float2* srow = sh[r];
    {
        int g = rt >> 5, bf = rt & 31;
        float2* s = srow + g*128;
        __syncthreads();
        { int j = bf & 1, base = (bf >> 1)*8 + j;
          r4<false>(s, base, 2, g_tw[j*80], g_tw[j*160], g_tw[j*240]); }
        __syncthreads();
        { int j = bf & 7, base = (bf >> 3)*32 + j;
          r4<false>(s, base, 8, g_tw[j*20], g_tw[j*40], g_tw[j*60]); }
        __syncthreads();
        r4<false>(s, bf, 32, g_tw[bf*5], g_tw[bf*10], g_tw[bf*15]);
        __syncthreads();
        if (rt < 128) {
            float2 z[5];
            z[0] = srow[rt];
            #pragma unroll
            for (int n1 = 1; n1 < 5; n1++)
                z[n1] = cmulw<false>(srow[n1*128 + rt], g_tw[n1*rt]);
            const float W5R[5] = {1.f, 0.309016994374947f, -0.809016994374947f, -0.809016994374947f, 0.309016994374947f};
            const float W5I[5] = {0.f, 0.951056516295154f, 0.587785252292473f, -0.587785252292473f, -0.951056516295154f};
            float* gf = (float*)g_buf;
            int pbase = u*5120 + b;           // (u*640 + v)*8 + b with v added below
            #pragma unroll
            for (int k1 = 0; k1 < 5; k1++) {
                float ar = z[0].x, ai = z[0].y;
                #pragma unroll
                for (int n1 = 1; n1 < 5; n1++) {
                    int q = (n1 * k1) % 5;
                    float wr = W5R[q], wi = -W5I[q];
                    ar += wr*z[n1].x - wi*z[n1].y;
                    ai += wr*z[n1].y + wi*z[n1].x;
                }
                int idx = pbase + (rt + 128*k1)*8;
                gf[XR0F + idx] = ar;
                gf[XI0F + idx] = ai;
            }
        }
    }
}

// ---------------- KB i0 and split-plane gather ----------------
__device__ __forceinline__ float i0f(float x) {
    if (x < 3.75f) {
        float t = x * (1.0f/3.75f); float t2 = t*t;
        return 1.0f + t2*(3.5156229f + t2*(3.0899424f + t2*(1.2067492f +
               t2*(0.2659732f + t2*(0.0360768f + t2*0.0045813f)))));
    } else {
        float t = 3.75f / x;
        float p = 0.39894228f + t*(0.01328592f + t*(0.00225319f + t*(-0.00157565f +
                  t*(0.00916281f + t*(-0.02057706f + t*(0.02635537f +
                  t*(-0.01647633f + t*0.00392377f)))))));
        return __expf(x) * rsqrtf(x) * p;
    }
}

// Per tap: q=(ix+iy)&3 selects plane (q&1: Xi else Xr) and sign (+ for q=0,3; - for q=1,2).
// out_re += kbx*kby*sgn * plane[(u*640+v)*8 + 0..7]  (2x LDG.128 per tap for all 8 batches)
__global__ __launch_bounds__(256) void k_gather(const float* __restrict__ tkx,
                                                const float* __restrict__ tky,
                                                float* __restrict__ out) {
    int p = blockIdx.x*256 + threadIdx.x;
    if (p >= 512000) return;
    const float beta = (float)(3.141592653589793 * sqrt(19.45));
    const float inv_i0b = 1.0f / i0f(beta);
    float gx = __ldg(&tkx[p]) * 2.0f;
    float gy = __ldg(&tky[p]) * 2.0f;
    if (!(gx > -321.f && gx < 321.f)) gx = 0.f;
    if (!(gy > -321.f && gy < 321.f)) gy = 0.f;
    int ix0 = (int)floorf(gx) - 2;
    int iy0 = (int)floorf(gy) - 2;
    float kbx[6], kby[6];
    int qx[6], qy[6], ixm[6], iym[6];
    #pragma unroll
    for (int j = 0; j < 6; j++) {
        {
            float d = gx - (float)(ix0 + j);
            float arg = fmaxf(1.0f - d*d*(1.0f/9.0f), 0.0f);
            kbx[j] = i0f(beta * sqrtf(arg)) * inv_i0b;
            qx[j] = (ix0 + j + 1024) & 3;
            int v = ix0 + j; if (v < 0) v += 640;
            ixm[j] = v;
        }
        {
            float d = gy - (float)(iy0 + j);
            float arg = fmaxf(1.0f - d*d*(1.0f/9.0f), 0.0f);
            kby[j] = i0f(beta * sqrtf(arg)) * inv_i0b;
            qy[j] = (iy0 + j + 1024) & 3;
            int v = iy0 + j; if (v < 0) v += 640;
            iym[j] = v;
        }
    }
    const float* gf = (const float*)g_buf;
    const float* xr = gf + XR0F;
    const float* xi = gf + XI0F;
    float acc0=0.f, acc1=0.f, acc2=0.f, acc3=0.f;
    float acc4=0.f, acc5=0.f, acc6=0.f, acc7=0.f;
    #pragma unroll
    for (int jx = 0; jx < 6; jx++) {
        int rb = ixm[jx]*5120;
        float wx = kbx[jx];
        int qxj = qx[jx];
        #pragma unroll
        for (int jy = 0; jy < 6; jy++) {
            int q = (qxj + qy[jy]) & 3;
            float coef = wx * kby[jy];
            coef = (q == 0 || q == 3) ? coef : -coef;
            const float* plane = (q & 1) ? xi : xr;
            const float4* cell = (const float4*)(plane + rb + iym[jy]*8);
            float4 v0 = __ldg(&cell[0]);
            float4 v1 = __ldg(&cell[1]);
            acc0 += coef*v0.x;
            acc1 += coef*v0.y;
            acc2 += coef*v0.z;
            acc3 += coef*v0.w;
            acc4 += coef*v1.x;
            acc5 += coef*v1.y;
            acc6 += coef*v1.z;
            acc7 += coef*v1.w;
        }
    }
    out[            p] = acc0;
    out[ 512000 + p] = acc1;
    out[1024000 + p] = acc2;
    out[1536000 + p] = acc3;
    out[2048000 + p] = acc4;
    out[2560000 + p] = acc5;
    out[3072000 + p] = acc6;
    out[3584000 + p] = acc7;
}

// ---------------- host launcher ----------------
extern "C" void kernel_launch(void* const* d_in, const int* in_sizes, int n_in,
                              void* d_out, int out_size) {
    const float *kr = 0, *ki = 0, *tkx = 0, *tky = 0;
    for (int i = 0; i < n_in; i++) {
        int s = in_sizes[i];
        if (s == 819200) {
            if (!kr) kr = (const float*)d_in[i];
            else if (!ki) ki = (const float*)d_in[i];
        } else if (s == 512000) {
            if (!tkx) tkx = (const float*)d_in[i];
            else if (!tky) tky = (const float*)d_in[i];
        }
    }
    if ((!kr || !ki || !tkx || !tky) && n_in >= 4) {
        kr  = (const float*)d_in[0];
        ki  = (const float*)d_in[1];
        tkx = (const float*)d_in[2];
        tky = (const float*)d_in[3];
    }
    if (!kr || !ki || !tkx || !tky || !d_out) return;
    float* out = (float*)d_out;

    k_init<<<1, 640>>>();
    k_ifft320_a<<<dim3(160, 8), 160>>>(kr, ki);
    k_trans320<<<dim3(10, 10, 8), dim3(32, 8)>>>();
    k_ifft320_b<<<dim3(160, 8), 160>>>();
    k_reduce<<<dim3(25, 8), 256>>>();
    k_fin<<<1, 32>>>();
    k_fft640_a<<<dim3(160, 8), 320>>>();
    k_trans640<<<dim3(20, 10, 8), dim3(32, 8)>>>();
    k_fft640_b<<<dim3(320, 8), 320>>>();
    k_gather<<<2000, 256>>>(tkx, tky, out);
}

// round 16
// speedup vs baseline: 2.1765x; 1.3603x over previous
#include <cuda_runtime.h>
#include <cuda_fp16.h>
#include <math.h>

// ---------------- static scratch ----------------
// float2 units: A[0,819200) B[819200,1638400) C[1638400,3276800) D[3276800,4915200)
#define OFF_A 0
#define OFF_B 819200
#define OFF_C 1638400
#define OFF_D 3276800
#define NBUF  4915200
#define XPLANE 3276800     // halves per plane (640*640*8)

__device__ float2 g_buf[NBUF];
__device__ __half g_xh[2*XPLANE];   // [0]=real plane, [1]=imag plane; layout (u*640+v)*8 + b
__device__ float4 g_part[200];      // [b][25] stats partials
__device__ float4 g_norm[8];
__device__ float  g_apinv[320];
__device__ float2 g_tw[640];        // W640^m = (cos, -sin)(2pi m/640)

// ---------------- init ----------------
__global__ void k_init() {
    int t = threadIdx.x;
    if (t < 640) {
        double a = 2.0 * 3.141592653589793 * (double)t / 640.0;
        double c, s; sincos(a, &s, &c);
        g_tw[t] = make_float2((float)c, (float)(-s));
    }
    if (t < 320) {
        double beta = 3.141592653589793 * sqrt(19.45);
        double f = (t - 160.0) / 640.0;
        double w6f = 3.141592653589793 * 6.0 * f;
        double arg = beta*beta - w6f*w6f;
        double z = sqrt(arg);
        double a = sinh(z) / z;
        double a0 = sinh(beta) / beta;
        g_apinv[t] = (float)(a0 / a);
    }
}

// ---------------- complex helpers ----------------
template<bool CONJ>
__device__ __forceinline__ float2 cmulw(float2 v, float2 w) {
    float wy = CONJ ? -w.y : w.y;
    return make_float2(v.x*w.x - v.y*wy, v.x*wy + v.y*w.x);
}

template<bool CONJ>
__device__ __forceinline__ void r4(float2* s, int base, int L,
                                   float2 w1, float2 w2, float2 w3) {
    float2 t0 = s[base];
    float2 t1 = cmulw<CONJ>(s[base+L],   w1);
    float2 t2 = cmulw<CONJ>(s[base+2*L], w2);
    float2 t3 = cmulw<CONJ>(s[base+3*L], w3);
    float e0r=t0.x+t2.x, e0i=t0.y+t2.y;
    float e1r=t0.x-t2.x, e1i=t0.y-t2.y;
    float o0r=t1.x+t3.x, o0i=t1.y+t3.y;
    float o1r=t1.x-t3.x, o1i=t1.y-t3.y;
    s[base]     = make_float2(e0r+o0r, e0i+o0i);
    s[base+2*L] = make_float2(e0r-o0r, e0i-o0i);
    if (!CONJ) {
        s[base+L]   = make_float2(e1r+o1i, e1i-o1r);
        s[base+3*L] = make_float2(e1r-o1i, e1i+o1r);
    } else {
        s[base+L]   = make_float2(e1r-o1i, e1i+o1r);
        s[base+3*L] = make_float2(e1r+o1i, e1i-o1r);
    }
}

__device__ __forceinline__ int drev4(int j) {
    return ((j & 3) << 4) | (j & 12) | (j >> 4);
}

// ---------------- 320-pt FFT stages ----------------
template<bool CONJ>
__device__ __forceinline__ void fft320_stages(float2* srow, int rt, int obase) {
    int g = rt >> 4, bf = rt & 15;
    float2* s = srow + g*64;
    __syncthreads();
    r4<CONJ>(s, bf*4, 1, g_tw[0], g_tw[0], g_tw[0]);
    __syncthreads();
    {
        int j = bf & 3, base = (bf >> 2)*16 + j;
        r4<CONJ>(s, base, 4, g_tw[j*40], g_tw[j*80], g_tw[j*120]);
    }
    __syncthreads();
    r4<CONJ>(s, bf, 16, g_tw[bf*10], g_tw[bf*20], g_tw[bf*30]);
    __syncthreads();
    if (rt < 64) {
        float2 z[5];
        z[0] = srow[rt];
        #pragma unroll
        for (int n1 = 1; n1 < 5; n1++)
            z[n1] = cmulw<CONJ>(srow[n1*64 + rt], g_tw[2*n1*rt]);
        const float W5R[5] = {1.f, 0.309016994374947f, -0.809016994374947f, -0.809016994374947f, 0.309016994374947f};
        const float W5I[5] = {0.f, 0.951056516295154f, 0.587785252292473f, -0.587785252292473f, -0.951056516295154f};
        const float s5 = CONJ ? 1.f : -1.f;
        #pragma unroll
        for (int k1 = 0; k1 < 5; k1++) {
            float ar = z[0].x, ai = z[0].y;
            #pragma unroll
            for (int n1 = 1; n1 < 5; n1++) {
                int q = (n1 * k1) % 5;
                float wr = W5R[q], wi = s5 * W5I[q];
                ar += wr*z[n1].x - wi*z[n1].y;
                ai += wr*z[n1].y + wi*z[n1].x;
            }
            g_buf[obase + rt + 64*k1] = make_float2(ar, ai);
        }
    }
}

// ---------------- phase 1 ----------------
__global__ __launch_bounds__(160) void k_ifft320_a(const float* __restrict__ kr,
                                                   const float* __restrict__ ki) {
    __shared__ float2 sh[2][320];
    int r = threadIdx.x / 80, rt = threadIdx.x % 80;
    int b = blockIdx.y, u = blockIdx.x*2 + r;
    int rowbase = (b*320 + u)*320;
    #pragma unroll
    for (int i = 0; i < 4; i++) {
        int e = rt + 80*i;
        int g = e >> 6, j = e & 63;
        int src = rowbase + g + 5*drev4(j);
        sh[r][e] = make_float2(__ldg(&kr[src]), __ldg(&ki[src]));
    }
    fft320_stages<true>(sh[r], rt, OFF_A + rowbase);
}

__global__ __launch_bounds__(160) void k_ifft320_b() {
    __shared__ float2 sh[2][320];
    int r = threadIdx.x / 80, rt = threadIdx.x % 80;
    int b = blockIdx.y, y = blockIdx.x*2 + r;
    int rowbase = (b*320 + y)*320;
    #pragma unroll
    for (int i = 0; i < 4; i++) {
        int e = rt + 80*i;
        int g = e >> 6, j = e & 63;
        sh[r][e] = g_buf[OFF_B + rowbase + g + 5*drev4(j)];
    }
    fft320_stages<true>(sh[r], rt, OFF_A + rowbase);
}

// ---------------- transposes ----------------
__global__ void k_trans320() {
    __shared__ float2 tile[32][33];
    int b = blockIdx.z;
    int base = b*320*320;
    int c = blockIdx.x*32 + threadIdx.x;
    int r0 = blockIdx.y*32;
    #pragma unroll
    for (int i = threadIdx.y; i < 32; i += 8)
        tile[i][threadIdx.x] = g_buf[OFF_A + base + (r0 + i)*320 + c];
    __syncthreads();
    int oc = r0 + threadIdx.x;
    int or0 = blockIdx.x*32;
    #pragma unroll
    for (int i = threadIdx.y; i < 32; i += 8)
        g_buf[OFF_B + base + (or0 + i)*320 + oc] = tile[threadIdx.x][i];
}

// C [b][y][u] -> D [b][u][y]
__global__ void k_trans640() {
    __shared__ float2 tile[32][33];
    int b = blockIdx.z;
    int c = blockIdx.x*32 + threadIdx.x;
    int r0 = blockIdx.y*32;
    #pragma unroll
    for (int i = threadIdx.y; i < 32; i += 8)
        tile[i][threadIdx.x] = g_buf[OFF_C + b*320*640 + (r0 + i)*640 + c];
    __syncthreads();
    int oc = r0 + threadIdx.x;
    int or0 = blockIdx.x*32;
    #pragma unroll
    for (int i = threadIdx.y; i < 32; i += 8)
        g_buf[OFF_D + b*640*320 + (or0 + i)*320 + oc] = tile[threadIdx.x][i];
}

// ---------------- reduction ----------------
__global__ __launch_bounds__(256) void k_reduce() {
    __shared__ float4 warpsum[8];
    int b = blockIdx.y;
    float sR = 0.f, sR2 = 0.f, sI = 0.f, sI2 = 0.f;
    int base = blockIdx.x*4096;
    #pragma unroll
    for (int i = 0; i < 16; i++) {
        int idx = base + threadIdx.x + i*256;
        float2 v = g_buf[OFF_A + b*102400 + idx];
        int y = idx / 320;
        int x = idx - y*320;
        float sg = ((x + y) & 1) ? -1.f : 1.f;
        sR  += sg * v.x;
        sR2 += v.x * v.x;
        sI  += sg * v.y;
        sI2 += v.y * v.y;
    }
    #pragma unroll
    for (int o = 16; o > 0; o >>= 1) {
        sR  += __shfl_down_sync(0xffffffff, sR,  o);
        sR2 += __shfl_down_sync(0xffffffff, sR2, o);
        sI  += __shfl_down_sync(0xffffffff, sI,  o);
        sI2 += __shfl_down_sync(0xffffffff, sI2, o);
    }
    int lane = threadIdx.x & 31, wid = threadIdx.x >> 5;
    if (lane == 0) warpsum[wid] = make_float4(sR, sR2, sI, sI2);
    __syncthreads();
    if (threadIdx.x == 0) {
        float4 t = warpsum[0];
        #pragma unroll
        for (int w = 1; w < 8; w++) {
            float4 u = warpsum[w];
            t.x += u.x; t.y += u.y; t.z += u.z; t.w += u.w;
        }
        g_part[b*25 + blockIdx.x] = t;
    }
}

__global__ void k_fin() {
    int b = threadIdx.x;
    if (b >= 8) return;
    double sR = 0, sR2 = 0, sI = 0, sI2 = 0;
    for (int j = 0; j < 25; j++) {
        float4 t = g_part[b*25 + j];
        sR += t.x; sR2 += t.y; sI += t.z; sI2 += t.w;
    }
    const double N = 102400.0;
    double sv_r = sR / 320.0;
    double sq_r = sR2 / 102400.0;
    double sv_i = sI / 320.0;
    double sq_i = sI2 / 102400.0;
    double mR = sv_r / N;
    double vR = (sq_r - sv_r*sv_r/N) / (N - 1.0);
    double mI = sv_i / N;
    double vI = (sq_i - sv_i*sv_i/N) / (N - 1.0);
    g_norm[b] = make_float4((float)mR, (float)(1.0/sqrt(vR)),
                            (float)mI, (float)(1.0/sqrt(vI)));
}

// ---------------- phase 2a: FFT along x ----------------
__global__ __launch_bounds__(320) void k_fft640_a() {
    __shared__ float2 sh[2][640];
    int r = threadIdx.x / 160, rt = threadIdx.x % 160;
    int b = blockIdx.y, y = blockIdx.x*2 + r;
    float4 nm = g_norm[b];
    int yy = (y < 160) ? y + 160 : y - 160;
    float apy = g_apinv[y];
    #pragma unroll
    for (int i = 0; i < 2; i++) {
        int pk = rt + 160*i;
        int g = pk >> 6, k = pk & 63;
        int x = g + 5*drev4(k);
        int xx = (x < 160) ? x + 160 : x - 160;
        float2 p = g_buf[OFF_A + (b*320 + yy)*320 + xx];
        float c = ((x + y) & 1) ? -0.003125f : 0.003125f;
        float re = (c*p.x - nm.x) * nm.y;
        float im = (c*p.y - nm.z) * nm.w;
        float sc = apy * g_apinv[x];
        float2 v = make_float2(re*sc, im*sc);
        sh[r][g*128 + 2*k]     = v;
        sh[r][g*128 + 2*k + 1] = v;
    }
    float2* srow = sh[r];
    {
        int g = rt >> 5, bf = rt & 31;
        float2* s = srow + g*128;
        __syncthreads();
        { int j = bf & 1, base = (bf >> 1)*8 + j;
          r4<false>(s, base, 2, g_tw[j*80], g_tw[j*160], g_tw[j*240]); }
        __syncthreads();
        { int j = bf & 7, base = (bf >> 3)*32 + j;
          r4<false>(s, base, 8, g_tw[j*20], g_tw[j*40], g_tw[j*60]); }
        __syncthreads();
        r4<false>(s, bf, 32, g_tw[bf*5], g_tw[bf*10], g_tw[bf*15]);
        __syncthreads();
        if (rt < 128) {
            float2 z[5];
            z[0] = srow[rt];
            #pragma unroll
            for (int n1 = 1; n1 < 5; n1++)
                z[n1] = cmulw<false>(srow[n1*128 + rt], g_tw[n1*rt]);
            const float W5R[5] = {1.f, 0.309016994374947f, -0.809016994374947f, -0.809016994374947f, 0.309016994374947f};
            const float W5I[5] = {0.f, 0.951056516295154f, 0.587785252292473f, -0.587785252292473f, -0.951056516295154f};
            int obase = OFF_C + (b*320 + y)*640;
            #pragma unroll
            for (int k1 = 0; k1 < 5; k1++) {
                float ar = z[0].x, ai = z[0].y;
                #pragma unroll
                for (int n1 = 1; n1 < 5; n1++) {
                    int q = (n1 * k1) % 5;
                    float wr = W5R[q], wi = -W5I[q];
                    ar += wr*z[n1].x - wi*z[n1].y;
                    ai += wr*z[n1].y + wi*z[n1].x;
                }
                g_buf[obase + rt + 128*k1] = make_float2(ar, ai);
            }
        }
    }
}

// ---------------- phase 2b: FFT along y -> fp16 Xr/Xi planes ----------------
__global__ __launch_bounds__(320) void k_fft640_b() {
    __shared__ float2 sh[2][640];
    int r = threadIdx.x / 160, rt = threadIdx.x % 160;
    int b = blockIdx.y, u = blockIdx.x*2 + r;
    #pragma unroll
    for (int i = 0; i < 2; i++) {
        int pk = rt + 160*i;
        int g = pk >> 6, k = pk & 63;
        int src = g + 5*drev4(k);
        float2 v = g_buf[OFF_D + b*640*320 + u*320 + src];
        sh[r][g*128 + 2*k]     = v;
        sh[r][g*128 + 2*k + 1] = v;
    }
    float2* srow = sh[r];
    {
        int g = rt >> 5, bf = rt & 31;
        float2* s = srow + g*128;
        __syncthreads();
        { int j = bf & 1, base = (bf >> 1)*8 + j;
          r4<false>(s, base, 2, g_tw[j*80], g_tw[j*160], g_tw[j*240]); }
        __syncthreads();
        { int j = bf & 7, base = (bf >> 3)*32 + j;
          r4<false>(s, base, 8, g_tw[j*20], g_tw[j*40], g_tw[j*60]); }
        __syncthreads();
        r4<false>(s, bf, 32, g_tw[bf*5], g_tw[bf*10], g_tw[bf*15]);
        __syncthreads();
        if (rt < 128) {
            float2 z[5];
            z[0] = srow[rt];
            #pragma unroll
            for (int n1 = 1; n1 < 5; n1++)
                z[n1] = cmulw<false>(srow[n1*128 + rt], g_tw[n1*rt]);
            const float W5R[5] = {1.f, 0.309016994374947f, -0.809016994374947f, -0.809016994374947f, 0.309016994374947f};
            const float W5I[5] = {0.f, 0.951056516295154f, 0.587785252292473f, -0.587785252292473f, -0.951056516295154f};
            int pbase = u*5120 + b;
            #pragma unroll
            for (int k1 = 0; k1 < 5; k1++) {
                float ar = z[0].x, ai = z[0].y;
                #pragma unroll
                for (int n1 = 1; n1 < 5; n1++) {
                    int q = (n1 * k1) % 5;
                    float wr = W5R[q], wi = -W5I[q];
                    ar += wr*z[n1].x - wi*z[n1].y;
                    ai += wr*z[n1].y + wi*z[n1].x;
                }
                int idx = pbase + (rt + 128*k1)*8;
                g_xh[idx]          = __float2half_rn(ar);
                g_xh[XPLANE + idx] = __float2half_rn(ai);
            }
        }
    }
}

// ---------------- KB i0 and fp16 split-plane gather ----------------
__device__ __forceinline__ float i0f(float x) {
    if (x < 3.75f) {
        float t = x * (1.0f/3.75f); float t2 = t*t;
        return 1.0f + t2*(3.5156229f + t2*(3.0899424f + t2*(1.2067492f +
               t2*(0.2659732f + t2*(0.0360768f + t2*0.0045813f)))));
    } else {
        float t = 3.75f / x;
        float p = 0.39894228f + t*(0.01328592f + t*(0.00225319f + t*(-0.00157565f +
                  t*(0.00916281f + t*(-0.02057706f + t*(0.02635537f +
                  t*(-0.01647633f + t*0.00392377f)))))));
        return __expf(x) * rsqrtf(x) * p;
    }
}

// Per tap: q=(ix+iy)&3 -> plane (q&1 ? Xi : Xr), sign (+ for q=0,3; - for q=1,2).
// One 16 B LDG.128 per tap loads all 8 batches (fp16).
__global__ __launch_bounds__(256) void k_gather(const float* __restrict__ tkx,
                                                const float* __restrict__ tky,
                                                float* __restrict__ out) {
    int p = blockIdx.x*256 + threadIdx.x;
    if (p >= 512000) return;
    const float beta = (float)(3.141592653589793 * sqrt(19.45));
    const float inv_i0b = 1.0f / i0f(beta);
    float gx = __ldg(&tkx[p]) * 2.0f;
    float gy = __ldg(&tky[p]) * 2.0f;
    if (!(gx > -321.f && gx < 321.f)) gx = 0.f;
    if (!(gy > -321.f && gy < 321.f)) gy = 0.f;
    int ix0 = (int)floorf(gx) - 2;
    int iy0 = (int)floorf(gy) - 2;
    float kbx[6], kby[6];
    int qx[6], qy[6], ixm[6], iym[6];
    #pragma unroll
    for (int j = 0; j < 6; j++) {
        {
            float d = gx - (float)(ix0 + j);
            float arg = fmaxf(1.0f - d*d*(1.0f/9.0f), 0.0f);
            kbx[j] = i0f(beta * sqrtf(arg)) * inv_i0b;
            qx[j] = (ix0 + j + 1024) & 3;
            int v = ix0 + j; if (v < 0) v += 640;
            ixm[j] = v;
        }
        {
            float d = gy - (float)(iy0 + j);
            float arg = fmaxf(1.0f - d*d*(1.0f/9.0f), 0.0f);
            kby[j] = i0f(beta * sqrtf(arg)) * inv_i0b;
            qy[j] = (iy0 + j + 1024) & 3;
            int v = iy0 + j; if (v < 0) v += 640;
            iym[j] = v;
        }
    }
    float acc0=0.f, acc1=0.f, acc2=0.f, acc3=0.f;
    float acc4=0.f, acc5=0.f, acc6=0.f, acc7=0.f;
    #pragma unroll
    for (int jx = 0; jx < 6; jx++) {
        int rb = ixm[jx]*5120;
        float wx = kbx[jx];
        int qxj = qx[jx];
        #pragma unroll
        for (int jy = 0; jy < 6; jy++) {
            int q = (qxj + qy[jy]) & 3;
            float coef = wx * kby[jy];
            coef = (q == 0 || q == 3) ? coef : -coef;
            const __half* plane = g_xh + (q & 1)*XPLANE;
            float4 raw = __ldg((const float4*)(plane + rb + iym[jy]*8));
            const __half2* hp = (const __half2*)&raw;
            float2 f0 = __half22float2(hp[0]);
            float2 f1 = __half22float2(hp[1]);
            float2 f2 = __half22float2(hp[2]);
            float2 f3 = __half22float2(hp[3]);
            acc0 += coef*f0.x;
            acc1 += coef*f0.y;
            acc2 += coef*f1.x;
            acc3 += coef*f1.y;
            acc4 += coef*f2.x;
            acc5 += coef*f2.y;
            acc6 += coef*f3.x;
            acc7 += coef*f3.y;
        }
    }
    out[            p] = acc0;
    out[ 512000 + p] = acc1;
    out[1024000 + p] = acc2;
    out[1536000 + p] = acc3;
    out[2048000 + p] = acc4;
    out[2560000 + p] = acc5;
    out[3072000 + p] = acc6;
    out[3584000 + p] = acc7;
}

// ---------------- host launcher ----------------
extern "C" void kernel_launch(void* const* d_in, const int* in_sizes, int n_in,
                              void* d_out, int out_size) {
    const float *kr = 0, *ki = 0, *tkx = 0, *tky = 0;
    for (int i = 0; i < n_in; i++) {
        int s = in_sizes[i];
        if (s == 819200) {
            if (!kr) kr = (const float*)d_in[i];
            else if (!ki) ki = (const float*)d_in[i];
        } else if (s == 512000) {
            if (!tkx) tkx = (const float*)d_in[i];
            else if (!tky) tky = (const float*)d_in[i];
        }
    }
    if ((!kr || !ki || !tkx || !tky) && n_in >= 4) {
        kr  = (const float*)d_in[0];
        ki  = (const float*)d_in[1];
        tkx = (const float*)d_in[2];
        tky = (const float*)d_in[3];
    }
    if (!kr || !ki || !tkx || !tky || !d_out) return;
    float* out = (float*)d_out;

    k_init<<<1, 640>>>();
    k_ifft320_a<<<dim3(160, 8), 160>>>(kr, ki);
    k_trans320<<<dim3(10, 10, 8), dim3(32, 8)>>>();
    k_ifft320_b<<<dim3(160, 8), 160>>>();
    k_reduce<<<dim3(25, 8), 256>>>();
    k_fin<<<1, 32>>>();
    k_fft640_a<<<dim3(160, 8), 320>>>();
    k_trans640<<<dim3(20, 10, 8), dim3(32, 8)>>>();
    k_fft640_b<<<dim3(320, 8), 320>>>();
    k_gather<<<2000, 256>>>(tkx, tky, out);
}

// round 17
// speedup vs baseline: 2.3459x; 1.0779x over previous
#include <cuda_runtime.h>
#include <cuda_fp16.h>
#include <math.h>

// ---------------- static scratch ----------------
// float2 units: A[0,819200) B[819200,1638400) C[1638400,3276800) D[3276800,4915200)
#define OFF_A 0
#define OFF_B 819200
#define OFF_C 1638400
#define OFF_D 3276800
#define NBUF  4915200
#define XPLANE 3276800     // halves per plane (640*640*8)

__device__ float2 g_buf[NBUF];
__device__ __half g_xh[2*XPLANE];   // [0]=real plane, [1]=imag plane; layout (u*640+v)*8 + b
__device__ float4 g_part[200];      // [b][25] stats partials
__device__ float4 g_norm[8];
__device__ float  g_apinv[320];
__device__ float2 g_tw[640];        // W640^m = (cos, -sin)(2pi m/640)

// ---------------- init ----------------
__global__ void k_init() {
    int t = threadIdx.x;
    if (t < 640) {
        double a = 2.0 * 3.141592653589793 * (double)t / 640.0;
        double c, s; sincos(a, &s, &c);
        g_tw[t] = make_float2((float)c, (float)(-s));
    }
    if (t < 320) {
        double beta = 3.141592653589793 * sqrt(19.45);
        double f = (t - 160.0) / 640.0;
        double w6f = 3.141592653589793 * 6.0 * f;
        double arg = beta*beta - w6f*w6f;
        double z = sqrt(arg);
        double a = sinh(z) / z;
        double a0 = sinh(beta) / beta;
        g_apinv[t] = (float)(a0 / a);
    }
}

// ---------------- complex helpers ----------------
template<bool CONJ>
__device__ __forceinline__ float2 cmulw(float2 v, float2 w) {
    float wy = CONJ ? -w.y : w.y;
    return make_float2(v.x*w.x - v.y*wy, v.x*wy + v.y*w.x);
}

template<bool CONJ>
__device__ __forceinline__ void r4(float2* s, int base, int L,
                                   float2 w1, float2 w2, float2 w3) {
    float2 t0 = s[base];
    float2 t1 = cmulw<CONJ>(s[base+L],   w1);
    float2 t2 = cmulw<CONJ>(s[base+2*L], w2);
    float2 t3 = cmulw<CONJ>(s[base+3*L], w3);
    float e0r=t0.x+t2.x, e0i=t0.y+t2.y;
    float e1r=t0.x-t2.x, e1i=t0.y-t2.y;
    float o0r=t1.x+t3.x, o0i=t1.y+t3.y;
    float o1r=t1.x-t3.x, o1i=t1.y-t3.y;
    s[base]     = make_float2(e0r+o0r, e0i+o0i);
    s[base+2*L] = make_float2(e0r-o0r, e0i-o0i);
    if (!CONJ) {
        s[base+L]   = make_float2(e1r+o1i, e1i-o1r);
        s[base+3*L] = make_float2(e1r-o1i, e1i+o1r);
    } else {
        s[base+L]   = make_float2(e1r-o1i, e1i+o1r);
        s[base+3*L] = make_float2(e1r+o1i, e1i-o1r);
    }
}

// register radix-4 (unit twiddles; caller pre-twiddles if needed)
template<bool CONJ>
__device__ __forceinline__ void r4reg(float2& a0, float2& a1, float2& a2, float2& a3) {
    float e0r=a0.x+a2.x, e0i=a0.y+a2.y;
    float e1r=a0.x-a2.x, e1i=a0.y-a2.y;
    float o0r=a1.x+a3.x, o0i=a1.y+a3.y;
    float o1r=a1.x-a3.x, o1i=a1.y-a3.y;
    a0 = make_float2(e0r+o0r, e0i+o0i);
    a2 = make_float2(e0r-o0r, e0i-o0i);
    if (!CONJ) {
        a1 = make_float2(e1r+o1i, e1i-o1r);
        a3 = make_float2(e1r-o1i, e1i+o1r);
    } else {
        a1 = make_float2(e1r-o1i, e1i+o1r);
        a3 = make_float2(e1r+o1i, e1i-o1r);
    }
}

// ---------------- 320-pt FFT tail: stages L=4, L=16, then radix-5 ----------------
// caller has already done stage 0 (L=1) into sh; rt in [0,80)
template<bool CONJ>
__device__ __forceinline__ void fft320_tail(float2* srow, int rt, int obase) {
    int g = rt >> 4, bf = rt & 15;
    float2* s = srow + g*64;
    __syncthreads();
    {
        int j = bf & 3, base = (bf >> 2)*16 + j;
        r4<CONJ>(s, base, 4, g_tw[j*40], g_tw[j*80], g_tw[j*120]);
    }
    __syncthreads();
    r4<CONJ>(s, bf, 16, g_tw[bf*10], g_tw[bf*20], g_tw[bf*30]);
    __syncthreads();
    if (rt < 64) {
        float2 z[5];
        z[0] = srow[rt];
        #pragma unroll
        for (int n1 = 1; n1 < 5; n1++)
            z[n1] = cmulw<CONJ>(srow[n1*64 + rt], g_tw[2*n1*rt]);
        const float W5R[5] = {1.f, 0.309016994374947f, -0.809016994374947f, -0.809016994374947f, 0.309016994374947f};
        const float W5I[5] = {0.f, 0.951056516295154f, 0.587785252292473f, -0.587785252292473f, -0.951056516295154f};
        const float s5 = CONJ ? 1.f : -1.f;
        #pragma unroll
        for (int k1 = 0; k1 < 5; k1++) {
            float ar = z[0].x, ai = z[0].y;
            #pragma unroll
            for (int n1 = 1; n1 < 5; n1++) {
                int q = (n1 * k1) % 5;
                float wr = W5R[q], wi = s5 * W5I[q];
                ar += wr*z[n1].x - wi*z[n1].y;
                ai += wr*z[n1].y + wi*z[n1].x;
            }
            g_buf[obase + rt + 64*k1] = make_float2(ar, ai);
        }
    }
}

// ---------------- phase 1a: IFFT rows (stage-0 fused into load) ----------------
__global__ __launch_bounds__(160) void k_ifft320_a(const float* __restrict__ kr,
                                                   const float* __restrict__ ki) {
    __shared__ float2 sh[2][320];
    int r = threadIdx.x / 80, rt = threadIdx.x % 80;
    int b = blockIdx.y, u = blockIdx.x*2 + r;
    int rowbase = (b*320 + u)*320;
    int g = rt >> 4, bf = rt & 15;
    int sbase = rowbase + g + 5*((bf & 3)*4 + (bf >> 2));
    float2 x0 = make_float2(__ldg(&kr[sbase      ]), __ldg(&ki[sbase      ]));
    float2 x1 = make_float2(__ldg(&kr[sbase +  80]), __ldg(&ki[sbase +  80]));
    float2 x2 = make_float2(__ldg(&kr[sbase + 160]), __ldg(&ki[sbase + 160]));
    float2 x3 = make_float2(__ldg(&kr[sbase + 240]), __ldg(&ki[sbase + 240]));
    r4reg<true>(x0, x1, x2, x3);
    float2* s = sh[r] + g*64 + bf*4;
    s[0] = x0; s[1] = x1; s[2] = x2; s[3] = x3;
    fft320_tail<true>(sh[r], rt, OFF_A + rowbase);
}

// ---------------- phase 1b: IFFT cols ----------------
__global__ __launch_bounds__(160) void k_ifft320_b() {
    __shared__ float2 sh[2][320];
    int r = threadIdx.x / 80, rt = threadIdx.x % 80;
    int b = blockIdx.y, y = blockIdx.x*2 + r;
    int rowbase = (b*320 + y)*320;
    int g = rt >> 4, bf = rt & 15;
    int sbase = OFF_B + rowbase + g + 5*((bf & 3)*4 + (bf >> 2));
    float2 x0 = g_buf[sbase      ];
    float2 x1 = g_buf[sbase +  80];
    float2 x2 = g_buf[sbase + 160];
    float2 x3 = g_buf[sbase + 240];
    r4reg<true>(x0, x1, x2, x3);
    float2* s = sh[r] + g*64 + bf*4;
    s[0] = x0; s[1] = x1; s[2] = x2; s[3] = x3;
    fft320_tail<true>(sh[r], rt, OFF_A + rowbase);
}

// ---------------- transposes ----------------
__global__ void k_trans320() {
    __shared__ float2 tile[32][33];
    int b = blockIdx.z;
    int base = b*320*320;
    int c = blockIdx.x*32 + threadIdx.x;
    int r0 = blockIdx.y*32;
    #pragma unroll
    for (int i = threadIdx.y; i < 32; i += 8)
        tile[i][threadIdx.x] = g_buf[OFF_A + base + (r0 + i)*320 + c];
    __syncthreads();
    int oc = r0 + threadIdx.x;
    int or0 = blockIdx.x*32;
    #pragma unroll
    for (int i = threadIdx.y; i < 32; i += 8)
        g_buf[OFF_B + base + (or0 + i)*320 + oc] = tile[threadIdx.x][i];
}

// C [b][y][u] -> D [b][u][y]
__global__ void k_trans640() {
    __shared__ float2 tile[32][33];
    int b = blockIdx.z;
    int c = blockIdx.x*32 + threadIdx.x;
    int r0 = blockIdx.y*32;
    #pragma unroll
    for (int i = threadIdx.y; i < 32; i += 8)
        tile[i][threadIdx.x] = g_buf[OFF_C + b*320*640 + (r0 + i)*640 + c];
    __syncthreads();
    int oc = r0 + threadIdx.x;
    int or0 = blockIdx.x*32;
    #pragma unroll
    for (int i = threadIdx.y; i < 32; i += 8)
        g_buf[OFF_D + b*640*320 + (or0 + i)*320 + oc] = tile[threadIdx.x][i];
}

// ---------------- reduction ----------------
__global__ __launch_bounds__(256) void k_reduce() {
    __shared__ float4 warpsum[8];
    int b = blockIdx.y;
    float sR = 0.f, sR2 = 0.f, sI = 0.f, sI2 = 0.f;
    int base = blockIdx.x*4096;
    #pragma unroll
    for (int i = 0; i < 16; i++) {
        int idx = base + threadIdx.x + i*256;
        float2 v = g_buf[OFF_A + b*102400 + idx];
        int y = idx / 320;
        int x = idx - y*320;
        float sg = ((x + y) & 1) ? -1.f : 1.f;
        sR  += sg * v.x;
        sR2 += v.x * v.x;
        sI  += sg * v.y;
        sI2 += v.y * v.y;
    }
    #pragma unroll
    for (int o = 16; o > 0; o >>= 1) {
        sR  += __shfl_down_sync(0xffffffff, sR,  o);
        sR2 += __shfl_down_sync(0xffffffff, sR2, o);
        sI  += __shfl_down_sync(0xffffffff, sI,  o);
        sI2 += __shfl_down_sync(0xffffffff, sI2, o);
    }
    int lane = threadIdx.x & 31, wid = threadIdx.x >> 5;
    if (lane == 0) warpsum[wid] = make_float4(sR, sR2, sI, sI2);
    __syncthreads();
    if (threadIdx.x == 0) {
        float4 t = warpsum[0];
        #pragma unroll
        for (int w = 1; w < 8; w++) {
            float4 u = warpsum[w];
            t.x += u.x; t.y += u.y; t.z += u.z; t.w += u.w;
        }
        g_part[b*25 + blockIdx.x] = t;
    }
}

__global__ void k_fin() {
    int b = threadIdx.x;
    if (b >= 8) return;
    double sR = 0, sR2 = 0, sI = 0, sI2 = 0;
    for (int j = 0; j < 25; j++) {
        float4 t = g_part[b*25 + j];
        sR += t.x; sR2 += t.y; sI += t.z; sI2 += t.w;
    }
    const double N = 102400.0;
    double sv_r = sR / 320.0;
    double sq_r = sR2 / 102400.0;
    double sv_i = sI / 320.0;
    double sq_i = sI2 / 102400.0;
    double mR = sv_r / N;
    double vR = (sq_r - sv_r*sv_r/N) / (N - 1.0);
    double mI = sv_i / N;
    double vI = (sq_i - sv_i*sv_i/N) / (N - 1.0);
    g_norm[b] = make_float4((float)mR, (float)(1.0/sqrt(vR)),
                            (float)mI, (float)(1.0/sqrt(vI)));
}

// ---------------- 640-pt FFT tail: stages L=8, L=32, then radix-5 ----------------
// caller has done the (fused radix-2 + radix-4 L=2) stage into sh; rt in [0,160)
// TOC: 0 -> store contiguous C row at obase; 1 -> store fp16 planes, obase = u*5120 + b
template<int TOC>
__device__ __forceinline__ void fft640_tail(float2* srow, int rt, int obase) {
    int g = rt >> 5, bf = rt & 31;
    float2* s = srow + g*128;
    __syncthreads();
    {
        int j = bf & 7, base = (bf >> 3)*32 + j;
        r4<false>(s, base, 8, g_tw[j*20], g_tw[j*40], g_tw[j*60]);
    }
    __syncthreads();
    r4<false>(s, bf, 32, g_tw[bf*5], g_tw[bf*10], g_tw[bf*15]);
    __syncthreads();
    if (rt < 128) {
        float2 z[5];
        z[0] = srow[rt];
        #pragma unroll
        for (int n1 = 1; n1 < 5; n1++)
            z[n1] = cmulw<false>(srow[n1*128 + rt], g_tw[n1*rt]);
        const float W5R[5] = {1.f, 0.309016994374947f, -0.809016994374947f, -0.809016994374947f, 0.309016994374947f};
        const float W5I[5] = {0.f, 0.951056516295154f, 0.587785252292473f, -0.587785252292473f, -0.951056516295154f};
        #pragma unroll
        for (int k1 = 0; k1 < 5; k1++) {
            float ar = z[0].x, ai = z[0].y;
            #pragma unroll
            for (int n1 = 1; n1 < 5; n1++) {
                int q = (n1 * k1) % 5;
                float wr = W5R[q], wi = -W5I[q];
                ar += wr*z[n1].x - wi*z[n1].y;
                ai += wr*z[n1].y + wi*z[n1].x;
            }
            if (TOC == 0) {
                g_buf[obase + rt + 128*k1] = make_float2(ar, ai);
            } else {
                int idx = obase + (rt + 128*k1)*8;
                g_xh[idx]          = __float2half_rn(ar);
                g_xh[XPLANE + idx] = __float2half_rn(ai);
            }
        }
    }
}

// ---------------- phase 2a: FFT along x (fused dup-radix2 + first radix-4) ----------------
__global__ __launch_bounds__(320) void k_fft640_a() {
    __shared__ float2 sh[2][640];
    int r = threadIdx.x / 160, rt = threadIdx.x % 160;
    int b = blockIdx.y, y = blockIdx.x*2 + r;
    float4 nm = g_norm[b];
    int yy = (y < 160) ? y + 160 : y - 160;
    float apy = g_apinv[y];
    int g = rt >> 5, bf = rt & 31;
    int kk = bf >> 1, jj = bf & 1;
    int xb = g + 5*((kk & 3)*4 + (kk >> 2));
    const float2* Prow = g_buf + OFF_A + (b*320 + yy)*320;
    float2 x[4];
    #pragma unroll
    for (int j = 0; j < 4; j++) {
        int xi = xb + 80*j;                       // value index in [0,320)
        int xx = (xi < 160) ? xi + 160 : xi - 160;
        float2 p = Prow[xx];
        float c = ((xi + y) & 1) ? -0.003125f : 0.003125f;
        float re = (c*p.x - nm.x) * nm.y;
        float im = (c*p.y - nm.z) * nm.w;
        float sc = apy * g_apinv[xi];
        x[j] = make_float2(re*sc, im*sc);
    }
    if (jj) {                                     // pre-twiddle for odd half
        x[1] = cmulw<false>(x[1], g_tw[80]);
        x[2] = cmulw<false>(x[2], g_tw[160]);
        x[3] = cmulw<false>(x[3], g_tw[240]);
    }
    r4reg<false>(x[0], x[1], x[2], x[3]);
    float2* s = sh[r] + g*128 + kk*8 + jj;
    s[0] = x[0]; s[2] = x[1]; s[4] = x[2]; s[6] = x[3];
    fft640_tail<0>(sh[r], rt, OFF_C + (b*320 + y)*640);
}

// ---------------- phase 2b: FFT along y -> fp16 planes (fused first stage) ----------------
__global__ __launch_bounds__(320) void k_fft640_b() {
    __shared__ float2 sh[2][640];
    int r = threadIdx.x / 160, rt = threadIdx.x % 160;
    int b = blockIdx.y, u = blockIdx.x*2 + r;
    int g = rt >> 5, bf = rt & 31;
    int kk = bf >> 1, jj = bf & 1;
    int sb = OFF_D + b*640*320 + u*320 + g + 5*((kk & 3)*4 + (kk >> 2));
    float2 x0 = g_buf[sb      ];
    float2 x1 = g_buf[sb +  80];
    float2 x2 = g_buf[sb + 160];
    float2 x3 = g_buf[sb + 240];
    if (jj) {
        x1 = cmulw<false>(x1, g_tw[80]);
        x2 = cmulw<false>(x2, g_tw[160]);
        x3 = cmulw<false>(x3, g_tw[240]);
    }
    r4reg<false>(x0, x1, x2, x3);
    float2* s = sh[r] + g*128 + kk*8 + jj;
    s[0] = x0; s[2] = x1; s[4] = x2; s[6] = x3;
    fft640_tail<1>(sh[r], rt, u*5120 + b);
}

// ---------------- KB i0 and fp16 split-plane gather ----------------
__device__ __forceinline__ float i0f(float x) {
    if (x < 3.75f) {
        float t = x * (1.0f/3.75f); float t2 = t*t;
        return 1.0f + t2*(3.5156229f + t2*(3.0899424f + t2*(1.2067492f +
               t2*(0.2659732f + t2*(0.0360768f + t2*0.0045813f)))));
    } else {
        float t = 3.75f / x;
        float p = 0.39894228f + t*(0.01328592f + t*(0.00225319f + t*(-0.00157565f +
                  t*(0.00916281f + t*(-0.02057706f + t*(0.02635537f +
                  t*(-0.01647633f + t*0.00392377f)))))));
        return __expf(x) * rsqrtf(x) * p;
    }
}

__global__ __launch_bounds__(256) void k_gather(const float* __restrict__ tkx,
                                                const float* __restrict__ tky,
                                                float* __restrict__ out) {
    int p = blockIdx.x*256 + threadIdx.x;
    if (p >= 512000) return;
    const float beta = (float)(3.141592653589793 * sqrt(19.45));
    const float inv_i0b = 1.0f / i0f(beta);
    float gx = __ldg(&tkx[p]) * 2.0f;
    float gy = __ldg(&tky[p]) * 2.0f;
    if (!(gx > -321.f && gx < 321.f)) gx = 0.f;
    if (!(gy > -321.f && gy < 321.f)) gy = 0.f;
    int ix0 = (int)floorf(gx) - 2;
    int iy0 = (int)floorf(gy) - 2;
    float kbx[6], kby[6];
    int qx[6], qy[6], ixm[6], iym[6];
    #pragma unroll
    for (int j = 0; j < 6; j++) {
        {
            float d = gx - (float)(ix0 + j);
            float arg = fmaxf(1.0f - d*d*(1.0f/9.0f), 0.0f);
            kbx[j] = i0f(beta * sqrtf(arg)) * inv_i0b;
            qx[j] = (ix0 + j + 1024) & 3;
            int v = ix0 + j; if (v < 0) v += 640;
            ixm[j] = v;
        }
        {
            float d = gy - (float)(iy0 + j);
            float arg = fmaxf(1.0f - d*d*(1.0f/9.0f), 0.0f);
            kby[j] = i0f(beta * sqrtf(arg)) * inv_i0b;
            qy[j] = (iy0 + j + 1024) & 3;
            int v = iy0 + j; if (v < 0) v += 640;
            iym[j] = v;
        }
    }
    float acc0=0.f, acc1=0.f, acc2=0.f, acc3=0.f;
    float acc4=0.f, acc5=0.f, acc6=0.f, acc7=0.f;
    #pragma unroll
    for (int jx = 0; jx < 6; jx++) {
        int rb = ixm[jx]*5120;
        float wx = kbx[jx];
        int qxj = qx[jx];
        #pragma unroll
        for (int jy = 0; jy < 6; jy++) {
            int q = (qxj + qy[jy]) & 3;
            float coef = wx * kby[jy];
            coef = (q == 0 || q == 3) ? coef : -coef;
            const __half* plane = g_xh + (q & 1)*XPLANE;
            float4 raw = __ldg((const float4*)(plane + rb + iym[jy]*8));
            const __half2* hp = (const __half2*)&raw;
            float2 f0 = __half22float2(hp[0]);
            float2 f1 = __half22float2(hp[1]);
            float2 f2 = __half22float2(hp[2]);
            float2 f3 = __half22float2(hp[3]);
            acc0 += coef*f0.x;
            acc1 += coef*f0.y;
            acc2 += coef*f1.x;
            acc3 += coef*f1.y;
            acc4 += coef*f2.x;
            acc5 += coef*f2.y;
            acc6 += coef*f3.x;
            acc7 += coef*f3.y;
        }
    }
    out[            p] = acc0;
    out[ 512000 + p] = acc1;
    out[1024000 + p] = acc2;
    out[1536000 + p] = acc3;
    out[2048000 + p] = acc4;
    out[2560000 + p] = acc5;
    out[3072000 + p] = acc6;
    out[3584000 + p] = acc7;
}

// ---------------- host launcher ----------------
extern "C" void kernel_launch(void* const* d_in, const int* in_sizes, int n_in,
                              void* d_out, int out_size) {
    const float *kr = 0, *ki = 0, *tkx = 0, *tky = 0;
    for (int i = 0; i < n_in; i++) {
        int s = in_sizes[i];
        if (s == 819200) {
            if (!kr) kr = (const float*)d_in[i];
            else if (!ki) ki = (const float*)d_in[i];
        } else if (s == 512000) {
            if (!tkx) tkx = (const float*)d_in[i];
            else if (!tky) tky = (const float*)d_in[i];
        }
    }
    if ((!kr || !ki || !tkx || !tky) && n_in >= 4) {
        kr  = (const float*)d_in[0];
        ki  = (const float*)d_in[1];
        tkx = (const float*)d_in[2];
        tky = (const float*)d_in[3];
    }
    if (!kr || !ki || !tkx || !tky || !d_out) return;
    float* out = (float*)d_out;

    k_init<<<1, 640>>>();
    k_ifft320_a<<<dim3(160, 8), 160>>>(kr, ki);
    k_trans320<<<dim3(10, 10, 8), dim3(32, 8)>>>();
    k_ifft320_b<<<dim3(160, 8), 160>>>();
    k_reduce<<<dim3(25, 8), 256>>>();
    k_fin<<<1, 32>>>();
    k_fft640_a<<<dim3(160, 8), 320>>>();
    k_trans640<<<dim3(20, 10, 8), dim3(32, 8)>>>();
    k_fft640_b<<<dim3(320, 8), 320>>>();
    k_gather<<<2000, 256>>>(tkx, tky, out);
}